// round 10
// baseline (speedup 1.0000x reference)
#include <cuda_runtime.h>

// Problem constants
#define FEAT      2048
#define FEAT4     512          // FEAT / 4
#define NNODES    50000
#define OUTN      256
#define GRID_Y    296          // 2 * 296 = 592 blocks = 4 full waves on 148 SMs
#define ROWS_PER  169          // ceil(50000 / 296)
#define NCHUNK    32
#define FCHUNK    64           // FEAT / NCHUNK

// Scratch (no runtime allocation allowed)
__device__ float g_partials[GRID_Y * FEAT];   // [y][f] partial column sums
__device__ float g_outp[NCHUNK * OUTN];       // per-f-chunk partial outputs

// K1: v_partial[y][f] = sum over rows in chunk y of adj[n] * fm[n][f]
// grid (2, GRID_Y), block 256. Each thread owns one float4 column group.
__global__ void __launch_bounds__(256, 8)
gemv_partial_kernel(const float* __restrict__ adj,
                    const float4* __restrict__ fm4) {
    __shared__ float s_adj[ROWS_PER];
    const int tid = threadIdx.x;
    const int c4  = blockIdx.x * 256 + tid;            // 0..511
    const int n0  = blockIdx.y * ROWS_PER;
    int rows = NNODES - n0;
    if (rows > ROWS_PER) rows = ROWS_PER;

    for (int i = tid; i < rows; i += 256) s_adj[i] = adj[n0 + i];
    __syncthreads();

    float4 acc = make_float4(0.f, 0.f, 0.f, 0.f);
    float4 acc2 = make_float4(0.f, 0.f, 0.f, 0.f);
    const float4* p = fm4 + (size_t)n0 * FEAT4 + c4;
    int r = 0;
    // 8-deep unroll: 8 independent in-flight 16B loads per thread (MLP)
    for (; r + 8 <= rows; r += 8) {
        float4 v0 = __ldg(p + 0 * FEAT4);
        float4 v1 = __ldg(p + 1 * FEAT4);
        float4 v2 = __ldg(p + 2 * FEAT4);
        float4 v3 = __ldg(p + 3 * FEAT4);
        float4 v4 = __ldg(p + 4 * FEAT4);
        float4 v5 = __ldg(p + 5 * FEAT4);
        float4 v6 = __ldg(p + 6 * FEAT4);
        float4 v7 = __ldg(p + 7 * FEAT4);
        float a0 = s_adj[r + 0], a1 = s_adj[r + 1];
        float a2 = s_adj[r + 2], a3 = s_adj[r + 3];
        float a4 = s_adj[r + 4], a5 = s_adj[r + 5];
        float a6 = s_adj[r + 6], a7 = s_adj[r + 7];
        acc.x  += a0 * v0.x; acc.y  += a0 * v0.y; acc.z  += a0 * v0.z; acc.w  += a0 * v0.w;
        acc2.x += a1 * v1.x; acc2.y += a1 * v1.y; acc2.z += a1 * v1.z; acc2.w += a1 * v1.w;
        acc.x  += a2 * v2.x; acc.y  += a2 * v2.y; acc.z  += a2 * v2.z; acc.w  += a2 * v2.w;
        acc2.x += a3 * v3.x; acc2.y += a3 * v3.y; acc2.z += a3 * v3.z; acc2.w += a3 * v3.w;
        acc.x  += a4 * v4.x; acc.y  += a4 * v4.y; acc.z  += a4 * v4.z; acc.w  += a4 * v4.w;
        acc2.x += a5 * v5.x; acc2.y += a5 * v5.y; acc2.z += a5 * v5.z; acc2.w += a5 * v5.w;
        acc.x  += a6 * v6.x; acc.y  += a6 * v6.y; acc.z  += a6 * v6.z; acc.w  += a6 * v6.w;
        acc2.x += a7 * v7.x; acc2.y += a7 * v7.y; acc2.z += a7 * v7.z; acc2.w += a7 * v7.w;
        p += 8 * FEAT4;
    }
    for (; r < rows; ++r) {
        float a = s_adj[r];
        float4 v = __ldg(p);
        acc.x += a * v.x; acc.y += a * v.y; acc.z += a * v.z; acc.w += a * v.w;
        p += FEAT4;
    }
    acc.x += acc2.x; acc.y += acc2.y; acc.z += acc2.z; acc.w += acc2.w;
    reinterpret_cast<float4*>(g_partials)[(size_t)blockIdx.y * FEAT4 + c4] = acc;
}

// K2: for each f-chunk (64 f's): sv[f] = A[f] * sum_y partials[y][f], then
// outp[chunk][o] = sum_f sv[f] * B[f][o]. grid NCHUNK=32, block 256.
__global__ void __launch_bounds__(256)
reduce_gemm_kernel(const float* __restrict__ A,
                   const float* __restrict__ B) {
    __shared__ float sv[FCHUNK];
    __shared__ float sh[4][FCHUNK];
    const int tid   = threadIdx.x;
    const int chunk = blockIdx.x;
    const int f     = tid & (FCHUNK - 1);   // 0..63
    const int quad  = tid >> 6;             // 0..3
    const int gf    = chunk * FCHUNK + f;

    // Phase 1: reduce GRID_Y partials for this chunk's f values (split over 4 quads)
    float s = 0.f;
    const int y0 = quad * (GRID_Y / 4);     // 296/4 = 74
    #pragma unroll 4
    for (int y = y0; y < y0 + GRID_Y / 4; ++y)
        s += g_partials[(size_t)y * FEAT + gf];
    sh[quad][f] = s;
    __syncthreads();
    if (quad == 0) sv[f] = A[gf] * (sh[0][f] + sh[1][f] + sh[2][f] + sh[3][f]);
    __syncthreads();

    // Phase 2: partial GEMM over this f-chunk; o = tid (coalesced B reads)
    float acc = 0.f;
    const float* Bp = B + (size_t)chunk * FCHUNK * OUTN + tid;
    #pragma unroll 8
    for (int ff = 0; ff < FCHUNK; ++ff)
        acc += sv[ff] * Bp[(size_t)ff * OUTN];
    g_outp[chunk * OUTN + tid] = acc;
}

// K3: out[o] = sum over chunks of partial outputs. 1 block, 256 threads.
__global__ void final_reduce_kernel(float* __restrict__ out) {
    const int o = threadIdx.x;
    float s = 0.f;
    #pragma unroll
    for (int c = 0; c < NCHUNK; ++c)
        s += g_outp[c * OUTN + o];
    out[o] = s;
}

extern "C" void kernel_launch(void* const* d_in, const int* in_sizes, int n_in,
                              void* d_out, int out_size) {
    const float*  adj = (const float*)d_in[0];   // [1, 50000]
    const float4* fm4 = (const float4*)d_in[1];  // [50000, 2048] fp32, viewed as float4
    const float*  A   = (const float*)d_in[2];   // [2048, 1]
    const float*  B   = (const float*)d_in[3];   // [2048, 256]
    // d_in[4] = fe_mask_rate = 0 (dropout identity) -> ignored
    float* out = (float*)d_out;                  // [1, 256]

    gemv_partial_kernel<<<dim3(2, GRID_Y), 256>>>(adj, fm4);
    reduce_gemm_kernel<<<NCHUNK, 256>>>(A, B);
    final_reduce_kernel<<<1, 256>>>(out);
}

// round 13
// speedup vs baseline: 1.1969x; 1.1969x over previous
#include <cuda_runtime.h>

// Problem constants
#define FEAT      2048
#define FEAT4     512          // FEAT / 4
#define NNODES    50000
#define OUTN      256
#define GRID_Y    592          // 2 * 592 = 1184 blocks = ONE full wave (148 SMs x 8 CTAs)
#define ROWS_PER  85           // ceil(50000 / 592); blocks past row 50000 write zeros
#define NCHUNK    64
#define FCHUNK    32           // FEAT / NCHUNK
#define YSEG      74           // GRID_Y / 8 y-rows reduced per thread-octant in K2

// Scratch (no runtime allocation allowed; zero-initialized at module load)
__device__ float g_partials[GRID_Y * FEAT];   // [y][f] partial column sums (4.85 MB)
__device__ float g_outp[NCHUNK * OUTN];       // per-f-chunk partial outputs

// K1: v_partial[y][f] = sum over rows in chunk y of adj[n] * fm[n][f]
// grid (2, GRID_Y), block 256. Each thread owns one float4 column group.
__global__ void __launch_bounds__(256, 8)
gemv_partial_kernel(const float* __restrict__ adj,
                    const float4* __restrict__ fm4) {
    __shared__ float s_adj[ROWS_PER];
    const int tid = threadIdx.x;
    const int c4  = blockIdx.x * 256 + tid;            // 0..511
    const int n0  = blockIdx.y * ROWS_PER;
    int rows = NNODES - n0;
    if (rows > ROWS_PER) rows = ROWS_PER;              // may be <= 0 for last blocks

    for (int i = tid; i < rows; i += 256) s_adj[i] = adj[n0 + i];
    __syncthreads();

    float4 acc = make_float4(0.f, 0.f, 0.f, 0.f);
    float4 acc2 = make_float4(0.f, 0.f, 0.f, 0.f);
    const float4* p = fm4 + (size_t)n0 * FEAT4 + c4;
    int r = 0;
    // 8-deep unroll: 8 independent in-flight 16B loads per thread (MLP)
    for (; r + 8 <= rows; r += 8) {
        float4 v0 = __ldg(p + 0 * FEAT4);
        float4 v1 = __ldg(p + 1 * FEAT4);
        float4 v2 = __ldg(p + 2 * FEAT4);
        float4 v3 = __ldg(p + 3 * FEAT4);
        float4 v4 = __ldg(p + 4 * FEAT4);
        float4 v5 = __ldg(p + 5 * FEAT4);
        float4 v6 = __ldg(p + 6 * FEAT4);
        float4 v7 = __ldg(p + 7 * FEAT4);
        float a0 = s_adj[r + 0], a1 = s_adj[r + 1];
        float a2 = s_adj[r + 2], a3 = s_adj[r + 3];
        float a4 = s_adj[r + 4], a5 = s_adj[r + 5];
        float a6 = s_adj[r + 6], a7 = s_adj[r + 7];
        acc.x  += a0 * v0.x; acc.y  += a0 * v0.y; acc.z  += a0 * v0.z; acc.w  += a0 * v0.w;
        acc2.x += a1 * v1.x; acc2.y += a1 * v1.y; acc2.z += a1 * v1.z; acc2.w += a1 * v1.w;
        acc.x  += a2 * v2.x; acc.y  += a2 * v2.y; acc.z  += a2 * v2.z; acc.w  += a2 * v2.w;
        acc2.x += a3 * v3.x; acc2.y += a3 * v3.y; acc2.z += a3 * v3.z; acc2.w += a3 * v3.w;
        acc.x  += a4 * v4.x; acc.y  += a4 * v4.y; acc.z  += a4 * v4.z; acc.w  += a4 * v4.w;
        acc2.x += a5 * v5.x; acc2.y += a5 * v5.y; acc2.z += a5 * v5.z; acc2.w += a5 * v5.w;
        acc.x  += a6 * v6.x; acc.y  += a6 * v6.y; acc.z  += a6 * v6.z; acc.w  += a6 * v6.w;
        acc2.x += a7 * v7.x; acc2.y += a7 * v7.y; acc2.z += a7 * v7.z; acc2.w += a7 * v7.w;
        p += 8 * FEAT4;
    }
    for (; r < rows; ++r) {
        float a = s_adj[r];
        float4 v = __ldg(p);
        acc.x += a * v.x; acc.y += a * v.y; acc.z += a * v.z; acc.w += a * v.w;
        p += FEAT4;
    }
    acc.x += acc2.x; acc.y += acc2.y; acc.z += acc2.z; acc.w += acc2.w;
    // Unconditional store: empty blocks (rows<=0) write zeros -> deterministic partials
    reinterpret_cast<float4*>(g_partials)[(size_t)blockIdx.y * FEAT4 + c4] = acc;
}

// K2: for each f-chunk (32 f's): sv[f] = A[f] * sum_y partials[y][f], then
// outp[chunk][o] = sum_f sv[f] * B[f][o]. grid NCHUNK=64, block 256.
// Thread layout: f = tid&31 (warp-coalesced 128B rows), yseg = tid>>5 (8 segs x 74 y).
__global__ void __launch_bounds__(256)
reduce_gemm_kernel(const float* __restrict__ A,
                   const float* __restrict__ B) {
    __shared__ float sv[FCHUNK];
    __shared__ float sh[8][FCHUNK];
    const int tid   = threadIdx.x;
    const int chunk = blockIdx.x;
    const int f     = tid & (FCHUNK - 1);   // 0..31
    const int yseg  = tid >> 5;             // 0..7
    const int gf    = chunk * FCHUNK + f;

    // Phase 1: reduce GRID_Y partials (8-way y-split, 74 rows/thread, unroll 8)
    float s = 0.f;
    const float* pp = g_partials + (size_t)(yseg * YSEG) * FEAT + gf;
    int y = 0;
    #pragma unroll
    for (; y + 8 <= YSEG; y += 8) {
        float t0 = pp[0 * FEAT], t1 = pp[1 * FEAT], t2 = pp[2 * FEAT], t3 = pp[3 * FEAT];
        float t4 = pp[4 * FEAT], t5 = pp[5 * FEAT], t6 = pp[6 * FEAT], t7 = pp[7 * FEAT];
        s += ((t0 + t1) + (t2 + t3)) + ((t4 + t5) + (t6 + t7));
        pp += 8 * FEAT;
    }
    for (; y < YSEG; ++y) { s += *pp; pp += FEAT; }
    sh[yseg][f] = s;
    __syncthreads();
    if (yseg == 0) {
        float t = ((sh[0][f] + sh[1][f]) + (sh[2][f] + sh[3][f]))
                + ((sh[4][f] + sh[5][f]) + (sh[6][f] + sh[7][f]));
        sv[f] = A[gf] * t;
    }
    __syncthreads();

    // Phase 2: partial GEMM over this f-chunk; o = tid (coalesced B reads)
    float acc = 0.f;
    const float* Bp = B + (size_t)chunk * FCHUNK * OUTN + tid;
    #pragma unroll
    for (int ff = 0; ff < FCHUNK; ++ff)
        acc += sv[ff] * Bp[(size_t)ff * OUTN];
    g_outp[chunk * OUTN + tid] = acc;
}

// K3: out[o] = sum over chunks of partial outputs. 1 block, 256 threads.
__global__ void final_reduce_kernel(float* __restrict__ out) {
    const int o = threadIdx.x;
    float s = 0.f;
    #pragma unroll
    for (int c = 0; c < NCHUNK; ++c)
        s += g_outp[c * OUTN + o];
    out[o] = s;
}

extern "C" void kernel_launch(void* const* d_in, const int* in_sizes, int n_in,
                              void* d_out, int out_size) {
    const float*  adj = (const float*)d_in[0];   // [1, 50000]
    const float4* fm4 = (const float4*)d_in[1];  // [50000, 2048] fp32, viewed as float4
    const float*  A   = (const float*)d_in[2];   // [2048, 1]
    const float*  B   = (const float*)d_in[3];   // [2048, 256]
    // d_in[4] = fe_mask_rate = 0 (dropout identity) -> ignored
    float* out = (float*)d_out;                  // [1, 256]

    gemv_partial_kernel<<<dim3(2, GRID_Y), 256>>>(adj, fm4);
    reduce_gemm_kernel<<<NCHUNK, 256>>>(A, B);
    final_reduce_kernel<<<1, 256>>>(out);
}

// round 14
// speedup vs baseline: 1.2006x; 1.0031x over previous
#include <cuda_runtime.h>

// Problem constants
#define FEAT      2048
#define FEAT4     512          // FEAT / 4
#define NNODES    50000
#define OUTN      256
#define GRID_Y    592          // 2 * 592 = 1184 blocks = ONE full wave (148 SMs x 8 CTAs)
#define BASE_ROWS 84           // 50000 = 592*84 + 272 -> first 272 y-chunks get 85 rows
#define EXTRA     272
#define MAX_ROWS  85
#define NCHUNK    64
#define FCHUNK    32           // FEAT / NCHUNK
#define YSEG      74           // GRID_Y / 8 y-rows reduced per thread-octant
#define TOTAL_BLOCKS (2 * GRID_Y)

// Scratch (no runtime allocation allowed; zero-initialized at module load)
__device__ float g_partials[GRID_Y * FEAT];   // [y][f] partial column sums (4.85 MB)
__device__ float g_outp[NCHUNK * OUTN];       // per-f-chunk partial outputs
__device__ int   g_c1;                        // K1-complete counter (reset each run)
__device__ int   g_c2;                        // reducer-complete counter (reset each run)

// Fused kernel: streaming GEMV partials -> device-wide sync -> reduce+GEMM -> final sum.
// grid (2, GRID_Y), block 256.
__global__ void __launch_bounds__(256, 8)
fused_kernel(const float* __restrict__ adj,
             const float4* __restrict__ fm4,
             const float* __restrict__ A,
             const float* __restrict__ B,
             float* __restrict__ out) {
    __shared__ float s_adj[MAX_ROWS];
    const int tid = threadIdx.x;
    const int yid = blockIdx.y;
    const int c4  = blockIdx.x * 256 + tid;            // 0..511
    // Balanced row partition: first EXTRA y-chunks take 85 rows, rest take 84.
    const int n0   = yid * BASE_ROWS + (yid < EXTRA ? yid : EXTRA);
    const int rows = BASE_ROWS + (yid < EXTRA ? 1 : 0);

    for (int i = tid; i < rows; i += 256) s_adj[i] = adj[n0 + i];
    __syncthreads();

    float4 acc = make_float4(0.f, 0.f, 0.f, 0.f);
    float4 acc2 = make_float4(0.f, 0.f, 0.f, 0.f);
    const float4* p = fm4 + (size_t)n0 * FEAT4 + c4;
    int r = 0;
    // 8-deep unroll: 8 independent in-flight 16B loads per thread (MLP)
    for (; r + 8 <= rows; r += 8) {
        float4 v0 = __ldg(p + 0 * FEAT4);
        float4 v1 = __ldg(p + 1 * FEAT4);
        float4 v2 = __ldg(p + 2 * FEAT4);
        float4 v3 = __ldg(p + 3 * FEAT4);
        float4 v4 = __ldg(p + 4 * FEAT4);
        float4 v5 = __ldg(p + 5 * FEAT4);
        float4 v6 = __ldg(p + 6 * FEAT4);
        float4 v7 = __ldg(p + 7 * FEAT4);
        float a0 = s_adj[r + 0], a1 = s_adj[r + 1];
        float a2 = s_adj[r + 2], a3 = s_adj[r + 3];
        float a4 = s_adj[r + 4], a5 = s_adj[r + 5];
        float a6 = s_adj[r + 6], a7 = s_adj[r + 7];
        acc.x  += a0 * v0.x; acc.y  += a0 * v0.y; acc.z  += a0 * v0.z; acc.w  += a0 * v0.w;
        acc2.x += a1 * v1.x; acc2.y += a1 * v1.y; acc2.z += a1 * v1.z; acc2.w += a1 * v1.w;
        acc.x  += a2 * v2.x; acc.y  += a2 * v2.y; acc.z  += a2 * v2.z; acc.w  += a2 * v2.w;
        acc2.x += a3 * v3.x; acc2.y += a3 * v3.y; acc2.z += a3 * v3.z; acc2.w += a3 * v3.w;
        acc.x  += a4 * v4.x; acc.y  += a4 * v4.y; acc.z  += a4 * v4.z; acc.w  += a4 * v4.w;
        acc2.x += a5 * v5.x; acc2.y += a5 * v5.y; acc2.z += a5 * v5.z; acc2.w += a5 * v5.w;
        acc.x  += a6 * v6.x; acc.y  += a6 * v6.y; acc.z  += a6 * v6.z; acc.w  += a6 * v6.w;
        acc2.x += a7 * v7.x; acc2.y += a7 * v7.y; acc2.z += a7 * v7.z; acc2.w += a7 * v7.w;
        p += 8 * FEAT4;
    }
    for (; r < rows; ++r) {
        float a = s_adj[r];
        float4 v = __ldg(p);
        acc.x += a * v.x; acc.y += a * v.y; acc.z += a * v.z; acc.w += a * v.w;
        p += FEAT4;
    }
    acc.x += acc2.x; acc.y += acc2.y; acc.z += acc2.z; acc.w += acc2.w;
    reinterpret_cast<float4*>(g_partials)[(size_t)yid * FEAT4 + c4] = acc;

    // Signal partials complete (one thread per block, after all stores drained)
    __syncthreads();
    __threadfence();
    if (tid == 0) atomicAdd(&g_c1, 1);

    // ---- Reducer role: blocks (x==0, y<64) handle one f-chunk each ----
    if (blockIdx.x != 0 || yid >= NCHUNK) return;
    const int chunk = yid;

    // Wait for ALL blocks' partials. Safe without cooperative launch: non-reducer
    // blocks exit after atomicAdd, freeing SM slots, so every block eventually runs.
    if (tid == 0) {
        while (atomicAdd(&g_c1, 0) < TOTAL_BLOCKS) __nanosleep(64);
    }
    __syncthreads();
    __threadfence();

    __shared__ float sv[FCHUNK];
    __shared__ float sh[8][FCHUNK];
    const int f    = tid & (FCHUNK - 1);   // 0..31
    const int yseg = tid >> 5;             // 0..7
    const int gf   = chunk * FCHUNK + f;

    // Phase 1: reduce GRID_Y partials (8-way y-split, 74 rows/thread, unroll 8)
    float s = 0.f;
    const float* pp = g_partials + (size_t)(yseg * YSEG) * FEAT + gf;
    int y = 0;
    #pragma unroll
    for (; y + 8 <= YSEG; y += 8) {
        float t0 = pp[0 * FEAT], t1 = pp[1 * FEAT], t2 = pp[2 * FEAT], t3 = pp[3 * FEAT];
        float t4 = pp[4 * FEAT], t5 = pp[5 * FEAT], t6 = pp[6 * FEAT], t7 = pp[7 * FEAT];
        s += ((t0 + t1) + (t2 + t3)) + ((t4 + t5) + (t6 + t7));
        pp += 8 * FEAT;
    }
    for (; y < YSEG; ++y) { s += *pp; pp += FEAT; }
    sh[yseg][f] = s;
    __syncthreads();
    if (yseg == 0) {
        float t = ((sh[0][f] + sh[1][f]) + (sh[2][f] + sh[3][f]))
                + ((sh[4][f] + sh[5][f]) + (sh[6][f] + sh[7][f]));
        sv[f] = A[gf] * t;
    }
    __syncthreads();

    // Phase 2: partial GEMM over this f-chunk; o = tid (coalesced B reads)
    float acc_o = 0.f;
    const float* Bp = B + (size_t)chunk * FCHUNK * OUTN + tid;
    #pragma unroll
    for (int ff = 0; ff < FCHUNK; ++ff)
        acc_o += sv[ff] * Bp[(size_t)ff * OUTN];
    g_outp[chunk * OUTN + tid] = acc_o;

    // Last reducer block performs the fixed-order final reduction (deterministic
    // result regardless of which block arrives last) and resets counters.
    __syncthreads();
    __threadfence();
    __shared__ int s_last;
    if (tid == 0) s_last = atomicAdd(&g_c2, 1);
    __syncthreads();
    if (s_last == NCHUNK - 1) {
        __threadfence();
        const int o = tid;
        float so = 0.f;
        #pragma unroll
        for (int c = 0; c < NCHUNK; ++c)
            so += g_outp[c * OUTN + o];
        out[o] = so;
        __syncthreads();
        if (tid == 0) { g_c1 = 0; g_c2 = 0; __threadfence(); }
    }
}

extern "C" void kernel_launch(void* const* d_in, const int* in_sizes, int n_in,
                              void* d_out, int out_size) {
    const float*  adj = (const float*)d_in[0];   // [1, 50000]
    const float4* fm4 = (const float4*)d_in[1];  // [50000, 2048] fp32, viewed as float4
    const float*  A   = (const float*)d_in[2];   // [2048, 1]
    const float*  B   = (const float*)d_in[3];   // [2048, 256]
    // d_in[4] = fe_mask_rate = 0 (dropout identity) -> ignored
    float* out = (float*)d_out;                  // [1, 256]

    fused_kernel<<<dim3(2, GRID_Y), 256>>>(adj, fm4, A, B, out);
}